// round 5
// baseline (speedup 1.0000x reference)
#include <cuda_runtime.h>
#include <cuda_bf16.h>

// ArcFaceLoss: N=8192 rows, C=32000 classes, fp32 pred, int target.
// loss_i = lse(logits_i) - S*margin(c_t)   where logits = 30*clamp(pred,-1,1),
// target column replaced by the arcface margin value.
// Trick: clamp bounds logits to [-30,30] -> fixed softmax max of 30, so a
// single streaming pass computes sum(exp(30c-30)); the target column is a
// rank-1 correction (one extra scalar load, L2-hit).

#define N_ROWS 8192
#define C_COLS 32000

__device__ float g_row_loss[N_ROWS];
__device__ int   g_tgt_is64;

// M = 0.5
#define COS_M      0.877582561890373f
#define SIN_M      0.479425538604203f
#define MM_CONST   0.239712769302101f     // sin(0.5)*0.5
#define THRESH    -0.877582561890373f     // -cos(0.5)
#define S_SCALE    30.0f
#define K2         43.28085122666891f     // 30*log2(e)

__device__ __forceinline__ float clamp1(float x) {
    return fminf(fmaxf(x, -1.0f), 1.0f);
}

__device__ __forceinline__ float eterm(float c) {
    // exp(30*c - 30) == exp2(K2*c - K2)
    return exp2f(fmaf(K2, c, -K2));
}

// ---------------------------------------------------------------------------
// Kernel 0: dtype sniff. int64 targets (< 32000) have all-zero high words;
// 64 random int32 targets all being zero has prob ~(1/32000)^64.
// 64 threads each load one odd word -> two ballots -> one DRAM round-trip
// instead of a 64-deep serial pointer-chase chain (was 4.3us in R1 profile).
__global__ void detect_tgt_kernel(const int* __restrict__ tgt) {
    int tid = threadIdx.x;                 // 0..63
    int hi = tgt[2 * tid + 1];
    unsigned nz = __ballot_sync(0xFFFFFFFFu, hi != 0);
    __shared__ unsigned part[2];
    part[tid >> 5] = nz;
    __syncthreads();
    if (tid == 0) g_tgt_is64 = (part[0] | part[1]) == 0u ? 1 : 0;
}

// ---------------------------------------------------------------------------
// Kernel 1: one block per row. 256 threads stream 32000 floats (float4,
// evict-first) and accumulate sum(exp(30*clamp(x)-30)). Block-reduce, then
// thread 0 applies the target-column margin correction.
__global__ __launch_bounds__(256) void row_loss_kernel(
    const float* __restrict__ pred,
    const void*  __restrict__ tgt)
{
    const int row = blockIdx.x;
    const int tid = threadIdx.x;
    const float4* __restrict__ p =
        reinterpret_cast<const float4*>(pred + (size_t)row * C_COLS);

    // 32000/4 = 8000 float4 per row
    float s0 = 0.0f, s1 = 0.0f;
    #pragma unroll 4
    for (int i = tid; i < C_COLS / 4; i += 256) {
        float4 v = __ldcs(&p[i]);
        s0 += eterm(clamp1(v.x)) + eterm(clamp1(v.y));
        s1 += eterm(clamp1(v.z)) + eterm(clamp1(v.w));
    }
    float s = s0 + s1;

    // block reduction: warp shuffle + smem
    __shared__ float warp_part[8];
    #pragma unroll
    for (int off = 16; off > 0; off >>= 1)
        s += __shfl_down_sync(0xFFFFFFFFu, s, off);
    if ((tid & 31) == 0) warp_part[tid >> 5] = s;
    __syncthreads();

    if (tid == 0) {
        float total = 0.0f;
        #pragma unroll
        for (int w = 0; w < 8; w++) total += warp_part[w];

        // target index (dtype-robust)
        long long t;
        if (g_tgt_is64) t = reinterpret_cast<const long long*>(tgt)[row];
        else            t = reinterpret_cast<const int*>(tgt)[row];

        float c = clamp1(pred[(size_t)row * C_COLS + t]);

        // arcface margin on the target cosine
        float tm;
        if (c > THRESH) {
            float sn = sqrtf(fmaxf(1.0f - c * c, 0.0f));
            tm = fmaf(c, COS_M, -sn * SIN_M);   // cos(acos(c)+M)
        } else {
            tm = c - MM_CONST;
        }

        // rank-1 correction: swap original target term for margin term
        float sum = total - eterm(c) + eterm(tm);

        // loss = lse - S*tm = (S + log(sum)) - S*tm
        g_row_loss[row] = S_SCALE + logf(sum) - S_SCALE * tm;
    }
}

// ---------------------------------------------------------------------------
// Kernel 2: mean of the 8192 row losses -> d_out[0]
__global__ __launch_bounds__(1024) void reduce_kernel(float* __restrict__ out) {
    const int tid = threadIdx.x;
    float s = 0.0f;
    #pragma unroll
    for (int i = tid; i < N_ROWS; i += 1024) s += g_row_loss[i];

    __shared__ float warp_part[32];
    #pragma unroll
    for (int off = 16; off > 0; off >>= 1)
        s += __shfl_down_sync(0xFFFFFFFFu, s, off);
    if ((tid & 31) == 0) warp_part[tid >> 5] = s;
    __syncthreads();

    if (tid < 32) {
        float v = warp_part[tid];
        #pragma unroll
        for (int off = 16; off > 0; off >>= 1)
            v += __shfl_down_sync(0xFFFFFFFFu, v, off);
        if (tid == 0) out[0] = v * (1.0f / (float)N_ROWS);
    }
}

// ---------------------------------------------------------------------------
extern "C" void kernel_launch(void* const* d_in, const int* in_sizes, int n_in,
                              void* d_out, int out_size)
{
    const float* pred = (const float*)d_in[0];
    const void*  tgt  = d_in[1];
    float* out = (float*)d_out;

    detect_tgt_kernel<<<1, 64>>>((const int*)tgt);
    row_loss_kernel<<<N_ROWS, 256>>>(pred, tgt);
    reduce_kernel<<<1, 1024>>>(out);
}